// round 2
// baseline (speedup 1.0000x reference)
#include <cuda_runtime.h>
#include <cstdint>

// Problem constants
#define SEQ_LEN  120
#define BATCH    2048
#define INPUT    6
#define HID      64
#define GATES    256
#define LAYERS   4
#define TLEN     120
#define NB       8             // batch per CTA
#define NCTA     (BATCH / NB)  // 256
#define NTHR     256           // 64 hh * 4 batch-groups (2 b each)

typedef unsigned long long ull;

// ------------- gate-interleaved weight scratch (device globals) ------------
// layout: [k][hh] as float4 {Wi, Wf, Wg, Wo}   (gate rows hh, 64+hh, 128+hh, 192+hh)
__device__ float4 g_eW04[INPUT * HID];                  // 384
__device__ float4 g_eWih4[(LAYERS - 1) * HID * HID];    // 12288
__device__ float4 g_eWhh4[LAYERS * HID * HID];          // 16384
__device__ float4 g_dW04[INPUT * HID];
__device__ float4 g_dWih4[(LAYERS - 1) * HID * HID];
__device__ float4 g_dWhh4[LAYERS * HID * HID];

#define N_W0   (INPUT * HID)
#define N_WIH  ((LAYERS - 1) * HID * HID)
#define N_WHH  (LAYERS * HID * HID)

__global__ void lstm36206574305735_pack(
    const float* __restrict__ eW0, const float* __restrict__ eWih,
    const float* __restrict__ eWhh, const float* __restrict__ dW0,
    const float* __restrict__ dWih, const float* __restrict__ dWhh)
{
    const int tot = 2 * (N_W0 + N_WIH + N_WHH);   // 58112 float4s
    for (int idx = blockIdx.x * blockDim.x + threadIdx.x; idx < tot;
         idx += gridDim.x * blockDim.x) {
        int r = idx;
        const float* src;
        float4* dst;
        int Kdim, k, hh;
        if (r < N_W0) { src = eW0; dst = g_eW04; Kdim = INPUT; }
        else if ((r -= N_W0) < N_W0) { src = dW0; dst = g_dW04; Kdim = INPUT; }
        else if ((r -= N_W0) < N_WIH) { src = eWih; dst = g_eWih4; Kdim = HID; }
        else if ((r -= N_WIH) < N_WIH) { src = dWih; dst = g_dWih4; Kdim = HID; }
        else if ((r -= N_WIH) < N_WHH) { src = eWhh; dst = g_eWhh4; Kdim = HID; }
        else { r -= N_WHH; src = dWhh; dst = g_dWhh4; Kdim = HID; }
        // r indexes [l][k][hh] with k*64+hh within layer of size 64*Kdim... careful:
        // per-layer float4 count = Kdim*HID; layer l = r / (Kdim*HID)
        int per = Kdim * HID;
        int l = r / per, rr = r % per;
        k = rr / HID; hh = rr % HID;
        const float* W = src + (size_t)l * GATES * Kdim;
        float4 v;
        v.x = W[(0 * HID + hh) * Kdim + k];
        v.y = W[(1 * HID + hh) * Kdim + k];
        v.z = W[(2 * HID + hh) * Kdim + k];
        v.w = W[(3 * HID + hh) * Kdim + k];
        dst[idx - (idx - (l * per + rr))] = v;   // == dst[l*per + rr]
    }
}

// ---------------- helpers ---------------------------------------------------
__device__ __forceinline__ void ffma2(ull& d, ull a, ull b) {
    asm("fma.rn.f32x2 %0, %1, %2, %0;" : "+l"(d) : "l"(a), "l"(b));
}
__device__ __forceinline__ ull pk(float a, float b) {
    ull v; asm("mov.b64 %0, {%1, %2};" : "=l"(v) : "f"(a), "f"(b)); return v;
}
__device__ __forceinline__ float2 unpk(ull v) {
    float2 r; asm("mov.b64 {%0, %1}, %2;" : "=f"(r.x), "=f"(r.y) : "l"(v)); return r;
}
__device__ __forceinline__ float fsig(float x) {
    return __fdividef(1.0f, 1.0f + __expf(-x));
}
__device__ __forceinline__ float ftanh_(float x) {
    return 2.0f * fsig(2.0f * x) - 1.0f;
}

// gemv: acc += W4[k][hh] (x) hdup[k][4bg..4bg+3]
template <int K>
__device__ __forceinline__ void gemv2(const ulonglong2* __restrict__ W,
                                      const float* __restrict__ hs,
                                      int hh, int bg,
                                      ull& aif0, ull& ago0, ull& aif1, ull& ago1)
{
#pragma unroll 8
    for (int k = 0; k < K; k++) {
        ulonglong2 wv = W[k * HID + hh];
        ulonglong2 hv = *(const ulonglong2*)(hs + k * 16 + bg * 4);
        ffma2(aif0, wv.x, hv.x);
        ffma2(ago0, wv.y, hv.x);
        ffma2(aif1, wv.x, hv.y);
        ffma2(ago1, wv.y, hv.y);
    }
}

// smem layout (floats)
#define OFF_HD   0                                   // [2][4][64][16]
#define SZ_HD    (2 * LAYERS * HID * 16)             // 8192
#define OFF_IN   (OFF_HD + SZ_HD)                    // [6][16] dup
#define SZ_IN    (INPUT * 16)                        // 96
#define OFF_LW   (OFF_IN + SZ_IN)                    // [hh][i] transposed
#define SZ_LW    (HID * INPUT)                       // 384
#define OFF_LB   (OFF_LW + SZ_LW)                    // 8
#define OFF_BIAS (OFF_LB + 8)                        // [2][4][64] ulonglong2 = 2048 floats
#define SZ_BIAS  (2 * LAYERS * HID * 4)
#define SMEM_FLOATS (OFF_BIAS + SZ_BIAS)             // 10728
#define SMEM_BYTES  (SMEM_FLOATS * 4)

__global__ void __launch_bounds__(NTHR, 2)
lstm36206574305735_main(const float* __restrict__ x,
                        const float* __restrict__ eB,
                        const float* __restrict__ dB,
                        const float* __restrict__ linW,
                        const float* __restrict__ linB,
                        float* __restrict__ out)
{
    extern __shared__ float smem[];
    float* hd   = smem + OFF_HD;
    float* ind  = smem + OFF_IN;
    float* lw_s = smem + OFF_LW;
    float* lb_s = smem + OFF_LB;
    ulonglong2* bias_s = (ulonglong2*)(smem + OFF_BIAS);

    const int tid = threadIdx.x;
    const int hh  = tid >> 2;       // 0..63
    const int bg  = tid & 3;        // 0..3  -> batch pair {2bg, 2bg+1}
    const int b0  = blockIdx.x * NB;

    // ---- init ----
    for (int i = tid; i < SZ_HD; i += NTHR) hd[i] = 0.0f;
    for (int i = tid; i < HID * INPUT; i += NTHR) {
        int h2 = i / INPUT, ii = i % INPUT;
        lw_s[h2 * INPUT + ii] = linW[ii * HID + h2];
    }
    if (tid < INPUT) lb_s[tid] = linB[tid];
    for (int u = tid; u < 2 * LAYERS * HID; u += NTHR) {
        int phase = u >> 8;
        int l = (u >> 6) & 3;
        int hx = u & 63;
        const float* B = phase ? dB : eB;
        ulonglong2 v;
        v.x = pk(B[l * GATES + hx],           B[l * GATES + HID + hx]);
        v.y = pk(B[l * GATES + 2 * HID + hx], B[l * GATES + 3 * HID + hx]);
        bias_s[u] = v;
    }

    float c_reg[LAYERS][2];
#pragma unroll
    for (int l = 0; l < LAYERS; l++) { c_reg[l][0] = 0.0f; c_reg[l][1] = 0.0f; }

    __syncthreads();

    const ulonglong2* eW0p  = (const ulonglong2*)g_eW04;
    const ulonglong2* eWihp = (const ulonglong2*)g_eWih4;
    const ulonglong2* eWhhp = (const ulonglong2*)g_eWhh4;
    const ulonglong2* dW0p  = (const ulonglong2*)g_dW04;
    const ulonglong2* dWihp = (const ulonglong2*)g_dWih4;
    const ulonglong2* dWhhp = (const ulonglong2*)g_dWhh4;

    // one time step through the stack; w = write-buffer parity
    auto step = [&](int phase, int w, const ulonglong2* W0p,
                    const ulonglong2* Wihp, const ulonglong2* Whhp) {
#pragma unroll
        for (int l = 0; l < LAYERS; l++) {
            ulonglong2 bv = bias_s[(phase * LAYERS + l) * HID + hh];
            ull aif0 = bv.x, ago0 = bv.y, aif1 = bv.x, ago1 = bv.y;

            if (l == 0) {
                gemv2<INPUT>(W0p, ind, hh, bg, aif0, ago0, aif1, ago1);
            } else {
                gemv2<HID>(Wihp + (l - 1) * HID * HID,
                           hd + ((w * LAYERS + (l - 1)) * HID) * 16,
                           hh, bg, aif0, ago0, aif1, ago1);
            }
            gemv2<HID>(Whhp + l * HID * HID,
                       hd + (((w ^ 1) * LAYERS + l) * HID) * 16,
                       hh, bg, aif0, ago0, aif1, ago1);

            // cell update (registers only), write dup h
            float* hrow = hd + ((w * LAYERS + l) * HID + hh) * 16;
#pragma unroll
            for (int bi = 0; bi < 2; bi++) {
                float2 sif = unpk(bi ? aif1 : aif0);
                float2 sgo = unpk(bi ? ago1 : ago0);
                float gi = fsig(sif.x), gf = fsig(sif.y);
                float gg = ftanh_(sgo.x), go = fsig(sgo.y);
                float c = fmaf(gf, c_reg[l][bi], gi * gg);
                c_reg[l][bi] = c;
                float h = go * ftanh_(c);
                *(float2*)(hrow + (bg * 2 + bi) * 2) = make_float2(h, h);
            }
            __syncthreads();
        }
    };

    // -------- encoder --------
    for (int t = 0; t < SEQ_LEN; t++) {
        if (tid < INPUT * NB) {
            int i = tid % INPUT, b = tid / INPUT;
            float v = x[((size_t)t * BATCH + b0 + b) * INPUT + i];
            ind[i * 16 + 2 * b] = v;
            ind[i * 16 + 2 * b + 1] = v;
        }
        __syncthreads();
        step(0, t & 1, eW0p, eWihp, eWhhp);
    }
    // ind holds x[SEQ_LEN-1] (decoder seed)

    // -------- decoder --------
    for (int t = 0; t < TLEN; t++) {
        int w = (SEQ_LEN + t) & 1;
        step(1, w, dW0p, dWihp, dWhhp);

        // projection: out[b][i] = lb[i] + sum_h lw[i][h] * htop[h][b]
        if (tid < INPUT * NB) {
            int i = tid % INPUT, b = tid / INPUT;
            const float* htop = hd + ((w * LAYERS + (LAYERS - 1)) * HID) * 16;
            float v = lb_s[i];
#pragma unroll 8
            for (int h2 = 0; h2 < HID; h2++)
                v += lw_s[h2 * INPUT + i] * htop[h2 * 16 + 2 * b];
            out[((size_t)t * BATCH + b0 + b) * INPUT + i] = v;
            ind[i * 16 + 2 * b] = v;
            ind[i * 16 + 2 * b + 1] = v;
        }
        __syncthreads();
    }
}

extern "C" void kernel_launch(void* const* d_in, const int* in_sizes, int n_in,
                              void* d_out, int out_size)
{
    const float* x    = (const float*)d_in[0];
    const float* eW0  = (const float*)d_in[1];
    const float* eWih = (const float*)d_in[2];
    const float* eWhh = (const float*)d_in[3];
    const float* eB   = (const float*)d_in[4];
    const float* dW0  = (const float*)d_in[5];
    const float* dWih = (const float*)d_in[6];
    const float* dWhh = (const float*)d_in[7];
    const float* dB   = (const float*)d_in[8];
    const float* linW = (const float*)d_in[9];
    const float* linB = (const float*)d_in[10];
    float* out = (float*)d_out;

    lstm36206574305735_pack<<<227, 256>>>(eW0, eWih, eWhh, dW0, dWih, dWhh);

    cudaFuncSetAttribute(lstm36206574305735_main,
                         cudaFuncAttributeMaxDynamicSharedMemorySize, SMEM_BYTES);
    lstm36206574305735_main<<<NCTA, NTHR, SMEM_BYTES>>>(x, eB, dB, linW, linB, out);
}

// round 3
// speedup vs baseline: 1.4448x; 1.4448x over previous
#include <cuda_runtime.h>
#include <cstdint>

#define SEQ_LEN  120
#define BATCH    2048
#define INPUT    6
#define HID      64
#define GATES    256
#define LAYERS   4
#define TLEN     120
#define NB       16            // batch per CTA
#define NCTA     (BATCH / NB)  // 128
#define NTHR     256           // 64 hh * 4 bg (4 batch each)

typedef unsigned long long ull;

// ---- gate-interleaved weights: [l][k][hh] float4 {Wi,Wf,Wg,Wo} -------------
__device__ float4 g_eW04[INPUT * HID];
__device__ float4 g_eWih4[(LAYERS - 1) * HID * HID];
__device__ float4 g_eWhh4[LAYERS * HID * HID];
__device__ float4 g_dW04[INPUT * HID];
__device__ float4 g_dWih4[(LAYERS - 1) * HID * HID];
__device__ float4 g_dWhh4[LAYERS * HID * HID];

#define N_W0   (INPUT * HID)
#define N_WIH  ((LAYERS - 1) * HID * HID)
#define N_WHH  (LAYERS * HID * HID)

__global__ void lstm36206574305735_pack(
    const float* __restrict__ eW0, const float* __restrict__ eWih,
    const float* __restrict__ eWhh, const float* __restrict__ dW0,
    const float* __restrict__ dWih, const float* __restrict__ dWhh)
{
    const int tot = 2 * (N_W0 + N_WIH + N_WHH);
    for (int idx = blockIdx.x * blockDim.x + threadIdx.x; idx < tot;
         idx += gridDim.x * blockDim.x) {
        int r = idx;
        const float* src; float4* dst; int Kdim;
        if (r < N_W0)                   { src = eW0;  dst = g_eW04;  Kdim = INPUT; }
        else if ((r -= N_W0)  < N_W0)   { src = dW0;  dst = g_dW04;  Kdim = INPUT; }
        else if ((r -= N_W0)  < N_WIH)  { src = eWih; dst = g_eWih4; Kdim = HID;   }
        else if ((r -= N_WIH) < N_WIH)  { src = dWih; dst = g_dWih4; Kdim = HID;   }
        else if ((r -= N_WIH) < N_WHH)  { src = eWhh; dst = g_eWhh4; Kdim = HID;   }
        else        { r -= N_WHH;         src = dWhh; dst = g_dWhh4; Kdim = HID;   }
        int per = Kdim * HID;
        int l = r / per, rr = r % per;
        int k = rr / HID, hh = rr % HID;
        const float* W = src + (size_t)l * GATES * Kdim;
        float4 v;
        v.x = W[(0 * HID + hh) * Kdim + k];
        v.y = W[(1 * HID + hh) * Kdim + k];
        v.z = W[(2 * HID + hh) * Kdim + k];
        v.w = W[(3 * HID + hh) * Kdim + k];
        dst[r] = v;
    }
}

// ---- helpers ----------------------------------------------------------------
__device__ __forceinline__ void ffma2(ull& d, ull a, ull b) {
    asm("fma.rn.f32x2 %0, %1, %2, %0;" : "+l"(d) : "l"(a), "l"(b));
}
__device__ __forceinline__ ull dup2(float a) {
    ull v; asm("mov.b64 %0, {%1, %1};" : "=l"(v) : "f"(a)); return v;
}
__device__ __forceinline__ ull pk(float a, float b) {
    ull v; asm("mov.b64 %0, {%1, %2};" : "=l"(v) : "f"(a), "f"(b)); return v;
}
__device__ __forceinline__ float2 unpk(ull v) {
    float2 r; asm("mov.b64 {%0, %1}, %2;" : "=f"(r.x), "=f"(r.y) : "l"(v)); return r;
}
__device__ __forceinline__ float fsig(float x) {
    return __fdividef(1.0f, 1.0f + __expf(-x));
}
__device__ __forceinline__ float ftanh_(float x) {
    return 2.0f * fsig(2.0f * x) - 1.0f;
}

// acc[8] = {i:b01, i:b23, f:b01, f:b23, g:b01, g:b23, o:b01, o:b23}
template <int K>
__device__ __forceinline__ void gemv4(const float4* __restrict__ W,
                                      const float* __restrict__ hs,
                                      int hh, int bg, ull acc[8])
{
#pragma unroll 8
    for (int k = 0; k < K; k++) {
        float4 w4 = __ldg(&W[k * HID + hh]);          // 1 coalesced LDG.128/warp
        ulonglong2 hv = *(const ulonglong2*)(hs + k * 16 + bg * 4); // broadcast LDS.128
        ull wi = dup2(w4.x), wf = dup2(w4.y), wg = dup2(w4.z), wo = dup2(w4.w);
        ffma2(acc[0], wi, hv.x); ffma2(acc[1], wi, hv.y);
        ffma2(acc[2], wf, hv.x); ffma2(acc[3], wf, hv.y);
        ffma2(acc[4], wg, hv.x); ffma2(acc[5], wg, hv.y);
        ffma2(acc[6], wo, hv.x); ffma2(acc[7], wo, hv.y);
    }
}

// ---- smem layout (floats) ---------------------------------------------------
#define OFF_HD   0                               // [2][4][64][16]
#define SZ_HD    (2 * LAYERS * HID * 16)         // 8192
#define OFF_IN   (OFF_HD + SZ_HD)                // [6][16]
#define SZ_IN    (INPUT * 16)                    // 96
#define OFF_LW   (OFF_IN + SZ_IN)                // [hh][i]
#define SZ_LW    (HID * INPUT)                   // 384
#define OFF_LB   (OFF_LW + SZ_LW)                // 8
#define OFF_BIAS (OFF_LB + 8)                    // [2][4][64] x 4 ull = 4096 floats
#define SZ_BIAS  (2 * LAYERS * HID * 8)
#define SMEM_FLOATS (OFF_BIAS + SZ_BIAS)
#define SMEM_BYTES  (SMEM_FLOATS * 4)

__global__ void __launch_bounds__(NTHR, 1)
lstm36206574305735_main(const float* __restrict__ x,
                        const float* __restrict__ eB,
                        const float* __restrict__ dB,
                        const float* __restrict__ linW,
                        const float* __restrict__ linB,
                        float* __restrict__ out)
{
    extern __shared__ float smem[];
    float* hd   = smem + OFF_HD;
    float* ind  = smem + OFF_IN;
    float* lw_s = smem + OFF_LW;
    float* lb_s = smem + OFF_LB;
    ull*   bias_s = (ull*)(smem + OFF_BIAS);     // [(phase*4+l)*64 + hh][4]

    const int tid = threadIdx.x;
    const int hh  = tid >> 2;     // 0..63
    const int bg  = tid & 3;      // batch quad {4bg .. 4bg+3}
    const int b0  = blockIdx.x * NB;

    for (int i = tid; i < SZ_HD; i += NTHR) hd[i] = 0.0f;
    for (int i = tid; i < HID * INPUT; i += NTHR) {
        int h2 = i / INPUT, ii = i % INPUT;
        lw_s[h2 * INPUT + ii] = linW[ii * HID + h2];
    }
    if (tid < INPUT) lb_s[tid] = linB[tid];
    for (int u = tid; u < 2 * LAYERS * HID; u += NTHR) {
        int phase = u >> 8, l = (u >> 6) & 3, hx = u & 63;
        const float* B = phase ? dB : eB;
        bias_s[u * 4 + 0] = dup2(B[l * GATES + hx]);
        bias_s[u * 4 + 1] = dup2(B[l * GATES + HID + hx]);
        bias_s[u * 4 + 2] = dup2(B[l * GATES + 2 * HID + hx]);
        bias_s[u * 4 + 3] = dup2(B[l * GATES + 3 * HID + hx]);
    }

    float c_reg[LAYERS][4];
#pragma unroll
    for (int l = 0; l < LAYERS; l++)
#pragma unroll
        for (int bi = 0; bi < 4; bi++) c_reg[l][bi] = 0.0f;

    __syncthreads();

    auto step = [&](int phase, int w, const float4* W0p,
                    const float4* Wihp, const float4* Whhp) {
#pragma unroll
        for (int l = 0; l < LAYERS; l++) {
            const ull* bv = bias_s + ((phase * LAYERS + l) * HID + hh) * 4;
            ull acc[8];
            acc[0] = acc[1] = bv[0];
            acc[2] = acc[3] = bv[1];
            acc[4] = acc[5] = bv[2];
            acc[6] = acc[7] = bv[3];

            if (l == 0) {
                gemv4<INPUT>(W0p, ind, hh, bg, acc);
            } else {
                gemv4<HID>(Wihp + (l - 1) * HID * HID,
                           hd + ((w * LAYERS + (l - 1)) * HID) * 16,
                           hh, bg, acc);
            }
            gemv4<HID>(Whhp + l * HID * HID,
                       hd + (((w ^ 1) * LAYERS + l) * HID) * 16,
                       hh, bg, acc);

            float2 ai0 = unpk(acc[0]), ai1 = unpk(acc[1]);
            float2 af0 = unpk(acc[2]), af1 = unpk(acc[3]);
            float2 ag0 = unpk(acc[4]), ag1 = unpk(acc[5]);
            float2 ao0 = unpk(acc[6]), ao1 = unpk(acc[7]);
            float ai[4] = {ai0.x, ai0.y, ai1.x, ai1.y};
            float af[4] = {af0.x, af0.y, af1.x, af1.y};
            float ag[4] = {ag0.x, ag0.y, ag1.x, ag1.y};
            float ao[4] = {ao0.x, ao0.y, ao1.x, ao1.y};

            float hout[4];
#pragma unroll
            for (int bi = 0; bi < 4; bi++) {
                float c = fmaf(fsig(af[bi]), c_reg[l][bi],
                               fsig(ai[bi]) * ftanh_(ag[bi]));
                c_reg[l][bi] = c;
                hout[bi] = fsig(ao[bi]) * ftanh_(c);
            }
            float* hrow = hd + ((w * LAYERS + l) * HID + hh) * 16 + bg * 4;
            *(float4*)hrow = make_float4(hout[0], hout[1], hout[2], hout[3]);
            __syncthreads();
        }
    };

    // -------- encoder --------
    for (int t = 0; t < SEQ_LEN; t++) {
        if (tid < INPUT * NB) {
            int b = tid / INPUT, i = tid % INPUT;
            ind[i * 16 + b] = x[((size_t)t * BATCH + b0 + b) * INPUT + i];
        }
        __syncthreads();
        step(0, t & 1, g_eW04, g_eWih4, g_eWhh4);
    }
    // ind holds x[SEQ_LEN-1] — decoder seed

    // -------- decoder --------
    for (int t = 0; t < TLEN; t++) {
        int w = (SEQ_LEN + t) & 1;
        step(1, w, g_dW04, g_dWih4, g_dWhh4);

        if (tid < INPUT * NB) {
            int b = tid / INPUT, i = tid % INPUT;
            const float* htop = hd + ((w * LAYERS + (LAYERS - 1)) * HID) * 16;
            float v = lb_s[i];
#pragma unroll 8
            for (int h2 = 0; h2 < HID; h2++)
                v += lw_s[h2 * INPUT + i] * htop[h2 * 16 + b];
            out[((size_t)t * BATCH + b0 + b) * INPUT + i] = v;
            ind[i * 16 + b] = v;
        }
        __syncthreads();
    }
}

extern "C" void kernel_launch(void* const* d_in, const int* in_sizes, int n_in,
                              void* d_out, int out_size)
{
    const float* x    = (const float*)d_in[0];
    const float* eW0  = (const float*)d_in[1];
    const float* eWih = (const float*)d_in[2];
    const float* eWhh = (const float*)d_in[3];
    const float* eB   = (const float*)d_in[4];
    const float* dW0  = (const float*)d_in[5];
    const float* dWih = (const float*)d_in[6];
    const float* dWhh = (const float*)d_in[7];
    const float* dB   = (const float*)d_in[8];
    const float* linW = (const float*)d_in[9];
    const float* linB = (const float*)d_in[10];
    float* out = (float*)d_out;

    lstm36206574305735_pack<<<227, 256>>>(eW0, eWih, eWhh, dW0, dWih, dWhh);

    cudaFuncSetAttribute(lstm36206574305735_main,
                         cudaFuncAttributeMaxDynamicSharedMemorySize, SMEM_BYTES);
    lstm36206574305735_main<<<NCTA, NTHR, SMEM_BYTES>>>(x, eB, dB, linW, linB, out);
}